// round 9
// baseline (speedup 1.0000x reference)
#include <cuda_runtime.h>
#include <math.h>

// Problem constants (fixed shapes from reference setup_inputs)
#define BATCH 16
#define CIN   128
#define C2    256     // 2*CIN (cos plane + sin plane)
#define COUT  256
#define HW    56
#define PIX   (HW*HW) // 3136
#define TAPS  9

typedef unsigned long long u64;

// Scratch (device globals: allocation-free per harness rules)
__device__ __align__(16) float g_inp[BATCH * C2 * PIX];        // [b][c2][y][x], 51.4 MB
__device__ __align__(16) float g_w[C2 * TAPS * 2 * COUT];      // [(c2*9+tap)*2+ri][cout], 4.7 MB

// ---- Blackwell packed f32x2 ops (two independent IEEE fp32 lanes) ----
__device__ __forceinline__ u64 fma2(u64 a, u64 b, u64 c) {
    u64 d;
    asm("fma.rn.f32x2 %0, %1, %2, %3;" : "=l"(d) : "l"(a), "l"(b), "l"(c));
    return d;
}
__device__ __forceinline__ u64 add2(u64 a, u64 b) {
    u64 d;
    asm("add.rn.f32x2 %0, %1, %2;" : "=l"(d) : "l"(a), "l"(b));
    return d;
}
// exact IEEE negation of both lanes
#define NEG2(x) ((x) ^ 0x8000000080000000ULL)

__device__ __forceinline__ void unpack2(u64 v, float& lo, float& hi) {
    asm("mov.b64 {%0, %1}, %2;" : "=f"(lo), "=f"(hi) : "l"(v));
}

// ---------------------------------------------------------------------------
// Merged prep kernel (2 launches per call total -> ncu -s 5 lands on ring_conv)
//  i < N1: input planes  cos(x)->[0,128), sin(x)->[128,256)   (pure fp32)
//  else  : trig weight products
// probe/out layout: (1, Cin, Cout, 1, 1, 3, 3) -> flat ((cin*COUT+cout)*9+tap)
// g_w row index for (c2, tap, ri): (c2*9 + tap)*2 + ri, row is COUT wide.
// ---------------------------------------------------------------------------
#define N1 (BATCH * CIN * PIX)
#define N2 (CIN * COUT * TAPS)

__global__ void prep_all(const float* __restrict__ x,
                         const float* __restrict__ probe,
                         const float* __restrict__ outang) {
    int i = blockIdx.x * blockDim.x + threadIdx.x;
    if (i < N1) {
        float v = x[i];
        int b   = i / (CIN * PIX);
        int rem = i % (CIN * PIX);
        int c   = rem / PIX;
        int p   = rem % PIX;
        float s, cs;
        sincosf(v, &s, &cs);
        g_inp[(b * C2 + c) * PIX + p]        = cs;
        g_inp[(b * C2 + c + CIN) * PIX + p]  = s;
    } else {
        int j = i - N1;
        if (j >= N2) return;
        int cin  = j / (COUT * TAPS);
        int rem  = j % (COUT * TAPS);
        int cout = rem / TAPS;
        int tap  = rem % TAPS;
        float p = probe[j];
        float o = outang[j];
        float sp, cp, so, co;
        sincosf(p, &sp, &cp);
        sincosf(o, &so, &co);
        g_w[(( cin        * TAPS + tap) * 2 + 0) * COUT + cout] = cp * co;
        g_w[(( cin        * TAPS + tap) * 2 + 1) * COUT + cout] = cp * so;
        g_w[(((cin + CIN) * TAPS + tap) * 2 + 0) * COUT + cout] = sp * co;
        g_w[(((cin + CIN) * TAPS + tap) * 2 + 1) * COUT + cout] = sp * so;
    }
}

// ---------------------------------------------------------------------------
// Main conv kernel: f32x2-packed FMAs over cout-pairs, chunked + Kahan
// (negated-compensation form), DOUBLE-BUFFERED smem pipeline:
// prefetch chunk N+1 (LDG) during compute of chunk N, STS into alternate
// buffer, single __syncthreads per chunk. Per-output op sequence is
// bit-identical to the round-6/7 kernels.
//
// Grid: (4 cout-quarters of 64, 49 spatial tiles of 8x8, 16 batch).
// Block: 256 threads = 16 cout-lanes x 16 pixel-lanes.
// ---------------------------------------------------------------------------
#define CHUNK 4
#define W_FLOATS (CHUNK * TAPS * 2 * 64)    // 4608 floats (64-cout slice)
#define W_VEC4   (W_FLOATS / 4)             // 1152 float4
#define IN_PTS   (CHUNK * 10 * 10)          // 400 halo points (stored as float2)
#define NCHUNK   (C2 / CHUNK)               // 64

__global__ __launch_bounds__(256)
void ring_conv(float* __restrict__ dout) {
    __shared__ __align__(16) float  s_w[2][W_FLOATS];
    __shared__ __align__(16) float2 s_in[2][IN_PTS];

    const int tid  = threadIdx.x;
    const int ct   = tid & 15;          // cout lane (4 couts each)
    const int pl   = tid >> 4;          // pixel lane 0..15
    const int row  = pl >> 1;           // 0..7
    const int colb = (pl & 1) * 4;      // 0 or 4

    const int coutBase = blockIdx.x * 64;
    const int t     = blockIdx.y;
    const int tileY = (t / 7) * 8;
    const int tileX = (t % 7) * 8;
    const int b     = blockIdx.z;

    // ---- prologue: fill buffer 0 with chunk 0 ----
    {
#pragma unroll
        for (int it = 0; it < 2; ++it) {
            int i = tid + it * 256;
            if (i < IN_PTS) {
                int icl = i / 100;
                int p   = i % 100;
                int gy  = tileY + p / 10 - 1;
                int gx  = tileX + p % 10 - 1;
                float v = 0.f;
                if ((unsigned)gy < (unsigned)HW && (unsigned)gx < (unsigned)HW)
                    v = g_inp[((b * C2 + icl) * HW + gy) * HW + gx];
                s_in[0][i] = make_float2(v, v);
            }
        }
#pragma unroll
        for (int it = 0; it < 5; ++it) {
            int i = tid + it * 256;          // float4 index
            if (i < W_VEC4) {
                int f   = i * 4;
                int icl = f / (TAPS * 2 * 64);
                int r   = (f % (TAPS * 2 * 64)) / 64;   // tap*2 + ri
                int col = f & 63;
                reinterpret_cast<float4*>(s_w[0])[i] =
                    *reinterpret_cast<const float4*>(
                        &g_w[(icl * 18 + r) * COUT + coutBase + col]);
            }
        }
    }
    __syncthreads();

    // s = main sum, nc = NEGATED Kahan compensation
    u64 sRe[2][4], sIm[2][4];
    u64 ncRe[2][4], ncIm[2][4];
#pragma unroll
    for (int jp = 0; jp < 2; ++jp)
#pragma unroll
        for (int k = 0; k < 4; ++k) {
            sRe[jp][k] = 0ull; sIm[jp][k] = 0ull;
            ncRe[jp][k] = 0ull; ncIm[jp][k] = 0ull;
        }

    int cur = 0;
    for (int chunk = 0; chunk < NCHUNK; ++chunk) {
        const bool havePre = (chunk + 1) < NCHUNK;
        const int ic0n = (chunk + 1) * CHUNK;

        // ---- issue next chunk's GMEM loads into registers (latency hidden
        //      under this chunk's compute) ----
        float  ipre[2];
        float4 wpre[5];
        if (havePre) {
#pragma unroll
            for (int it = 0; it < 2; ++it) {
                int i = tid + it * 256;
                if (i < IN_PTS) {
                    int icl = i / 100;
                    int p   = i % 100;
                    int gy  = tileY + p / 10 - 1;
                    int gx  = tileX + p % 10 - 1;
                    float v = 0.f;
                    if ((unsigned)gy < (unsigned)HW && (unsigned)gx < (unsigned)HW)
                        v = g_inp[((b * C2 + ic0n + icl) * HW + gy) * HW + gx];
                    ipre[it] = v;
                }
            }
#pragma unroll
            for (int it = 0; it < 5; ++it) {
                int i = tid + it * 256;
                if (i < W_VEC4) {
                    int f   = i * 4;
                    int icl = f / (TAPS * 2 * 64);
                    int r   = (f % (TAPS * 2 * 64)) / 64;
                    int col = f & 63;
                    wpre[it] = *reinterpret_cast<const float4*>(
                        &g_w[((ic0n + icl) * 18 + r) * COUT + coutBase + col]);
                }
            }
        }

        // ---- compute chunk partial (packed FMA, bit-identical order) ----
        u64 pRe[2][4], pIm[2][4];
#pragma unroll
        for (int jp = 0; jp < 2; ++jp)
#pragma unroll
            for (int k = 0; k < 4; ++k) { pRe[jp][k] = 0ull; pIm[jp][k] = 0ull; }

#pragma unroll
        for (int icl = 0; icl < CHUNK; ++icl) {
            const float2* in_base = &s_in[cur][icl * 100];
#pragma unroll
            for (int ky = 0; ky < 3; ++ky) {
                // 6 duplicated (v,v) operands, loaded as 3x LDS.128
                u64 vp[6];
                const ulonglong2* rp = reinterpret_cast<const ulonglong2*>(
                    &in_base[(row + ky) * 10 + colb]);
#pragma unroll
                for (int j = 0; j < 3; ++j) {
                    ulonglong2 q = rp[j];
                    vp[2 * j]     = q.x;
                    vp[2 * j + 1] = q.y;
                }
#pragma unroll
                for (int kx = 0; kx < 3; ++kx) {
                    const int tap = ky * 3 + kx;
                    const ulonglong2 wr = reinterpret_cast<const ulonglong2*>(
                        &s_w[cur][(icl * 18 + tap * 2 + 0) * 64])[ct];
                    const ulonglong2 wi = reinterpret_cast<const ulonglong2*>(
                        &s_w[cur][(icl * 18 + tap * 2 + 1) * 64])[ct];
                    u64 wra[2] = { wr.x, wr.y };
                    u64 wia[2] = { wi.x, wi.y };
#pragma unroll
                    for (int jp = 0; jp < 2; ++jp) {
#pragma unroll
                        for (int k = 0; k < 4; ++k) {
                            u64 xv = vp[k + kx];
                            // Re/Im pair shares b-operand xv -> reuse-cache hit
                            pRe[jp][k] = fma2(wra[jp], xv, pRe[jp][k]);
                            pIm[jp][k] = fma2(wia[jp], xv, pIm[jp][k]);
                        }
                    }
                }
            }
        }

        // ---- Kahan merge (negated-compensation; exact IEEE negation) ----
#pragma unroll
        for (int jp = 0; jp < 2; ++jp) {
#pragma unroll
            for (int k = 0; k < 4; ++k) {
                {
                    u64 y1 = add2(pRe[jp][k], ncRe[jp][k]);
                    u64 tt = add2(sRe[jp][k], y1);
                    ncRe[jp][k] = add2(add2(sRe[jp][k], NEG2(tt)), y1);
                    sRe[jp][k] = tt;
                }
                {
                    u64 y1 = add2(pIm[jp][k], ncIm[jp][k]);
                    u64 tt = add2(sIm[jp][k], y1);
                    ncIm[jp][k] = add2(add2(sIm[jp][k], NEG2(tt)), y1);
                    sIm[jp][k] = tt;
                }
            }
        }

        // ---- store prefetched chunk into the alternate buffer ----
        if (havePre) {
            const int nxt = cur ^ 1;
#pragma unroll
            for (int it = 0; it < 2; ++it) {
                int i = tid + it * 256;
                if (i < IN_PTS)
                    s_in[nxt][i] = make_float2(ipre[it], ipre[it]);
            }
#pragma unroll
            for (int it = 0; it < 5; ++it) {
                int i = tid + it * 256;
                if (i < W_VEC4)
                    reinterpret_cast<float4*>(s_w[nxt])[i] = wpre[it];
            }
        }
        __syncthreads();
        cur ^= 1;
    }

    // ---- epilogue: angle = atan2(im, re) ----
    const int y = tileY + row;
#pragma unroll
    for (int jp = 0; jp < 2; ++jp) {
#pragma unroll
        for (int lane = 0; lane < 2; ++lane) {
            const int cout = coutBase + ct * 4 + jp * 2 + lane;
            float* op = &dout[((b * COUT + cout) * HW + y) * HW + tileX + colb];
#pragma unroll
            for (int k = 0; k < 4; ++k) {
                float reLo, reHi, imLo, imHi;
                unpack2(sRe[jp][k], reLo, reHi);
                unpack2(sIm[jp][k], imLo, imHi);
                float re = lane ? reHi : reLo;
                float im = lane ? imHi : imLo;
                op[k] = atan2f(im, re);
            }
        }
    }
}

// ---------------------------------------------------------------------------
extern "C" void kernel_launch(void* const* d_in, const int* in_sizes, int n_in,
                              void* d_out, int out_size) {
    const float* x      = (const float*)d_in[0];
    const float* probe  = (const float*)d_in[1];
    const float* outang = (const float*)d_in[2];
    float* dout = (float*)d_out;

    (void)in_sizes; (void)n_in; (void)out_size;

    const int ntot = N1 + N2;
    prep_all<<<(ntot + 255) / 256, 256>>>(x, probe, outang);

    dim3 grid(4, 49, BATCH);
    ring_conv<<<grid, 256>>>(dout);
}